// round 15
// baseline (speedup 1.0000x reference)
#include <cuda_runtime.h>
#include <cuda_fp16.h>
#include <math.h>
#include <stdint.h>

typedef uint32_t u32;

#define MROWS 65536
#define NBLH  4096
#define OUT_ELEMS ((size_t)MROWS * 256)

// Scratch: fp16 pairs packed in u32 words (pairs along the k/d dimension)
__device__ u32 g_qh[(size_t)NBLH * 128 * 16];   // [blq][h][w][dk/2]
__device__ u32 g_kh[(size_t)NBLH * 128 * 16];
__device__ u32 g_vh[(size_t)NBLH * 128 * 16];
__device__ u32 g_attnout[(size_t)MROWS * 128];  // [m][d/2]
__device__ u32 g_wh[4 * 32768];                 // Wq,Wk,Wv,Wfc as fp16 pairs [n][k/2]

// ---------------------------------------------------------------------------
// helpers
// ---------------------------------------------------------------------------
__device__ __forceinline__ u32 f2h2(float lo, float hi) {
    __half2 h = __floats2half2_rn(lo, hi);
    return *reinterpret_cast<u32*>(&h);
}
__device__ __forceinline__ void mma_f16(float* d, const u32* a, u32 b0, u32 b1) {
    asm volatile(
        "mma.sync.aligned.m16n8k16.row.col.f32.f16.f16.f32 "
        "{%0,%1,%2,%3}, {%4,%5,%6,%7}, {%8,%9}, {%0,%1,%2,%3};"
        : "+f"(d[0]), "+f"(d[1]), "+f"(d[2]), "+f"(d[3])
        : "r"(a[0]), "r"(a[1]), "r"(a[2]), "r"(a[3]), "r"(b0), "r"(b1));
}
__device__ __forceinline__ void ldmx4(u32* r, u32 addr) {
    asm volatile("ldmatrix.sync.aligned.m8n8.x4.shared.b16 {%0,%1,%2,%3}, [%4];"
        : "=r"(r[0]), "=r"(r[1]), "=r"(r[2]), "=r"(r[3]) : "r"(addr));
}
__device__ __forceinline__ void ldmx4t(u32* r, u32 addr) {
    asm volatile("ldmatrix.sync.aligned.m8n8.x4.trans.shared.b16 {%0,%1,%2,%3}, [%4];"
        : "=r"(r[0]), "=r"(r[1]), "=r"(r[2]), "=r"(r[3]) : "r"(addr));
}
__device__ __forceinline__ u32 smem_u32(const void* p) {
    u32 a;
    asm("{ .reg .u64 t; cvta.to.shared.u64 t, %1; cvt.u32.u64 %0, t; }" : "=r"(a) : "l"(p));
    return a;
}
__device__ __forceinline__ void cp16(u32 dst, const void* src) {
    asm volatile("cp.async.cg.shared.global [%0], [%1], 16;" :: "r"(dst), "l"(src));
}
#define CP_COMMIT() asm volatile("cp.async.commit_group;")
#define CP_WAIT(n)  asm volatile("cp.async.wait_group %0;" :: "n"(n))

// row stride in u32 words for all [row][k] smem tiles (16 data + 4 pad)
#define SW 20

// ---------------------------------------------------------------------------
// Weight pre-conversion to packed fp16
// ---------------------------------------------------------------------------
__global__ void wconv(const float* __restrict__ Wq, const float* __restrict__ Wk,
                      const float* __restrict__ Wv, const float* __restrict__ Wfc)
{
    int i = blockIdx.x * 256 + threadIdx.x;   // 0..32767
    g_wh[i]             = f2h2(Wq[2 * i],  Wq[2 * i + 1]);
    g_wh[32768 + i]     = f2h2(Wk[2 * i],  Wk[2 * i + 1]);
    g_wh[2 * 32768 + i] = f2h2(Wv[2 * i],  Wv[2 * i + 1]);
    g_wh[3 * 32768 + i] = f2h2(Wfc[2 * i], Wfc[2 * i + 1]);
}

// ---------------------------------------------------------------------------
// Kernel A: QKV projection. 256 threads, 32-row m-tile, N=256, 8 warps (2x4),
// warp tile 16x64, BK=32, 2-stage pipeline. 3 CTAs/SM. grid (2048, 3).
// ---------------------------------------------------------------------------
#define PJ_A_STG (32 * SW)            // 640 words per A stage
#define PJ_B_STG (256 * SW)           // 5120 words per B stage
#define PJ_SMEM_BYTES ((2 * PJ_A_STG + 2 * PJ_B_STG) * 4)   // 46080

__global__ __launch_bounds__(256, 3) void gemm_proj(
    const float* __restrict__ q, const float* __restrict__ k, const float* __restrict__ v,
    const float* __restrict__ bq, const float* __restrict__ bk, const float* __restrict__ bv)
{
    extern __shared__ u32 dyn[];
    u32* As = dyn;                    // [2][32*SW]
    u32* Bs = dyn + 2 * PJ_A_STG;     // [2][256*SW]

    const int z = blockIdx.y;
    const float* X    = (z == 0) ? q : (z == 1) ? k : v;
    const u32*   Wt   = g_wh + (size_t)z * 32768;
    const float* bias = (z == 0) ? bq : (z == 1) ? bk : bv;
    u32*         outp = (z == 0) ? g_qh : (z == 1) ? g_kh : g_vh;
    const float scale = (z == 0) ? 0.17677669529663687f : 1.0f;

    const int tid  = threadIdx.x;
    const int wid  = tid >> 5;
    const int lane = tid & 31;
    const int g    = lane >> 2;
    const int t    = lane & 3;
    const int lr   = lane & 15;
    const int lc   = (lane >> 4) * 4;
    const int wm   = wid >> 2;     // 0..1
    const int wn   = wid & 3;      // 0..3
    const int m0   = blockIdx.x * 32;

    const u32 as_b = smem_u32(As);
    const u32 bs_b = smem_u32(Bs);

    const int arow = tid >> 3;     // 0..31 (8 threads per row)
    const int ac   = tid & 7;      // 4 floats each

    float4 fa;
#define LDG_A(cc)                                                              \
    fa = *(const float4*)&X[(size_t)(m0 + arow) * 256 + (cc) * 32 + ac * 4]
#define STS_A(st)                                                              \
    do {                                                                       \
        u32* _d = &As[(st) * PJ_A_STG + arow * SW + ac * 2];                   \
        _d[0] = f2h2(fa.x, fa.y); _d[1] = f2h2(fa.z, fa.w);                    \
    } while (0)
#define CP_B(st, cc)                                                           \
    do {                                                                       \
        _Pragma("unroll")                                                      \
        for (int _j = 0; _j < 4; _j++) {                                       \
            int _idx = tid + _j * 256; int _r = _idx >> 2, _c4 = _idx & 3;     \
            cp16(bs_b + (u32)((st) * PJ_B_STG + _r * SW + _c4 * 4) * 4,        \
                 &Wt[(size_t)_r * 128 + (cc) * 16 + _c4 * 4]);                 \
        }                                                                      \
    } while (0)

    // prologue
    LDG_A(0);
    CP_B(0, 0); CP_COMMIT();
    STS_A(0);
    LDG_A(1);
    CP_B(1, 1); CP_COMMIT();

    float acc[8][4];
    #pragma unroll
    for (int b = 0; b < 8; b++)
        #pragma unroll
        for (int c = 0; c < 4; c++) acc[b][c] = 0.0f;

    #pragma unroll 1
    for (int i = 0; i < 8; i++) {
        const int s = i & 1;
        if (i < 7) { CP_WAIT(1); } else { CP_WAIT(0); }
        __syncthreads();

        const u32 a0 = as_b + (u32)s * PJ_A_STG * 4;
        const u32 b0 = bs_b + (u32)s * PJ_B_STG * 4;
        #pragma unroll
        for (int c = 0; c < 2; c++) {
            u32 ra[4];
            ldmx4(ra, a0 + (u32)((wm * 16 + lr) * SW + c * 8 + lc) * 4);
            #pragma unroll
            for (int qq = 0; qq < 4; qq++) {
                u32 rb[4];
                ldmx4(rb, b0 + (u32)((wn * 64 + qq * 16 + lr) * SW + c * 8 + lc) * 4);
                mma_f16(acc[2 * qq],     ra, rb[0], rb[2]);
                mma_f16(acc[2 * qq + 1], ra, rb[1], rb[3]);
            }
        }

        if (i < 7) STS_A(s ^ 1);
        __syncthreads();
        if (i < 6) {
            LDG_A(i + 2);
            CP_B(s, i + 2);
            CP_COMMIT();
        }
    }

    // epilogue: bias, scale, pack fp16 pairs, scatter to [blq][h][w][dk/2]
    const int blq = blockIdx.x >> 2;
    const int qtr = (blockIdx.x & 3) * 32;
    #pragma unroll
    for (int nt = 0; nt < 8; nt++) {
        int n  = wn * 64 + nt * 8 + 2 * t;
        int h  = n >> 5;
        int dw = (n & 31) >> 1;
        float b0v = bias[n], b1v = bias[n + 1];
        #pragma unroll
        for (int rs = 0; rs < 2; rs++) {
            int ww = qtr + wm * 16 + g + 8 * rs;
            outp[(((size_t)blq * 8 + h) * 128 + ww) * 16 + dw] =
                f2h2((acc[nt][2 * rs]     + b0v) * scale,
                     (acc[nt][2 * rs + 1] + b1v) * scale);
        }
    }
}

// ---------------------------------------------------------------------------
// Kernel B: attention, 2 blocks per CTA, cp.async double-buffered QKV
// (round-11/14 version, unchanged).
// ---------------------------------------------------------------------------
#define AT_STG_W (3 * 128 * SW)               // 7680 words per stage (Q,K,V)
#define AT_SMEM_BYTES (2 * AT_STG_W * 4)      // 61440

__global__ __launch_bounds__(256, 2) void attn_kernel(float* __restrict__ attn_out)
{
    extern __shared__ u32 dyn[];
    const u32 sb = smem_u32(dyn);

    const int bid  = blockIdx.x;
    const int tid  = threadIdx.x;
    const int wid  = tid >> 5;
    const int lane = tid & 31;
    const int g    = lane >> 2;
    const int t    = lane & 3;
    const int lr   = lane & 15;
    const int lc   = (lane >> 4) * 4;

    // prologue: issue cp.async for both blocks' Q/K/V
    #pragma unroll
    for (int s = 0; s < 2; s++) {
        const size_t blk = (size_t)(bid * 2 + s);
        const u32* Qg = g_qh + blk * 2048;
        const u32* Kg = g_kh + blk * 2048;
        const u32* Vg = g_vh + blk * 2048;
        #pragma unroll
        for (int j = 0; j < 2; j++) {
            int idx = tid + j * 256;
            int row = idx >> 2, q4 = idx & 3;
            u32 off = sb + (u32)(s * AT_STG_W + row * SW + q4 * 4) * 4;
            cp16(off,                     Qg + idx * 4);
            cp16(off + 128 * SW * 4,      Kg + idx * 4);
            cp16(off + 2 * 128 * SW * 4,  Vg + idx * 4);
        }
        CP_COMMIT();
    }

    #pragma unroll 1
    for (int s = 0; s < 2; s++) {
        if (s == 0) { CP_WAIT(1); } else { CP_WAIT(0); }
        __syncthreads();

        const int blk  = bid * 2 + s;
        const u32 qs_b = sb + (u32)(s * AT_STG_W) * 4;
        const u32 ks_b = qs_b + 128 * SW * 4;
        const u32 vs_b = ks_b + 128 * SW * 4;

        float sacc[16][4];
        #pragma unroll
        for (int nt = 0; nt < 16; nt++)
            #pragma unroll
            for (int c = 0; c < 4; c++) sacc[nt][c] = 0.0f;

        const int rbase16 = wid * 16;
        const int rbase   = rbase16 + g;
        #pragma unroll
        for (int c = 0; c < 2; c++) {
            u32 ra[4];
            ldmx4(ra, qs_b + (u32)((rbase16 + lr) * SW + c * 8 + lc) * 4);
            #pragma unroll
            for (int qq = 0; qq < 8; qq++) {
                u32 rb[4];
                ldmx4(rb, ks_b + (u32)((qq * 16 + lr) * SW + c * 8 + lc) * 4);
                mma_f16(sacc[2 * qq],     ra, rb[0], rb[2]);
                mma_f16(sacc[2 * qq + 1], ra, rb[1], rb[3]);
            }
        }

        float inv[2];
        #pragma unroll
        for (int rs = 0; rs < 2; rs++) {
            float mx = -1e30f;
            #pragma unroll
            for (int nt = 0; nt < 16; nt++) {
                mx = fmaxf(mx, sacc[nt][2 * rs]);
                mx = fmaxf(mx, sacc[nt][2 * rs + 1]);
            }
            mx = fmaxf(mx, __shfl_xor_sync(0xffffffffu, mx, 1));
            mx = fmaxf(mx, __shfl_xor_sync(0xffffffffu, mx, 2));
            float ss = 0.0f;
            #pragma unroll
            for (int nt = 0; nt < 16; nt++) {
                float e0 = __expf(sacc[nt][2 * rs] - mx);
                float e1 = __expf(sacc[nt][2 * rs + 1] - mx);
                sacc[nt][2 * rs] = e0; sacc[nt][2 * rs + 1] = e1;
                ss += e0 + e1;
            }
            ss += __shfl_xor_sync(0xffffffffu, ss, 1);
            ss += __shfl_xor_sync(0xffffffffu, ss, 2);
            inv[rs] = 1.0f / ss;
        }
        #pragma unroll
        for (int nt = 0; nt < 16; nt++) {
            sacc[nt][0] *= inv[0]; sacc[nt][1] *= inv[0];
            sacc[nt][2] *= inv[1]; sacc[nt][3] *= inv[1];
        }

        const size_t abase = (size_t)blk * 16384;
        #pragma unroll
        for (int nt = 0; nt < 16; nt++) {
            int col = nt * 8 + 2 * t;
            float2 p0; p0.x = sacc[nt][0]; p0.y = sacc[nt][1];
            float2 p1; p1.x = sacc[nt][2]; p1.y = sacc[nt][3];
            *(float2*)&attn_out[abase + (size_t)rbase * 128 + col]       = p0;
            *(float2*)&attn_out[abase + (size_t)(rbase + 8) * 128 + col] = p1;
        }

        float oacc[4][4];
        #pragma unroll
        for (int nt = 0; nt < 4; nt++)
            #pragma unroll
            for (int c = 0; c < 4; c++) oacc[nt][c] = 0.0f;

        const int vrow_off = ((lane >> 3) & 1) * 8 + (lane & 7);
        const int vcol_off = (lane >> 4) * 4;
        #pragma unroll
        for (int ks = 0; ks < 8; ks++) {
            u32 af[4];
            af[0] = f2h2(sacc[2 * ks][0],     sacc[2 * ks][1]);
            af[1] = f2h2(sacc[2 * ks][2],     sacc[2 * ks][3]);
            af[2] = f2h2(sacc[2 * ks + 1][0], sacc[2 * ks + 1][1]);
            af[3] = f2h2(sacc[2 * ks + 1][2], sacc[2 * ks + 1][3]);
            #pragma unroll
            for (int np = 0; np < 2; np++) {
                u32 rb[4];
                ldmx4t(rb, vs_b + (u32)((16 * ks + vrow_off) * SW + np * 8 + vcol_off) * 4);
                mma_f16(oacc[2 * np],     af, rb[0], rb[1]);
                mma_f16(oacc[2 * np + 1], af, rb[2], rb[3]);
            }
        }

        const int blq = blk >> 3;
        const int h   = blk & 7;
        #pragma unroll
        for (int nt = 0; nt < 4; nt++) {
            #pragma unroll
            for (int rs = 0; rs < 2; rs++) {
                int m = blq * 128 + rbase + 8 * rs;
                g_attnout[(size_t)m * 128 + h * 16 + nt * 4 + t] =
                    f2h2(oacc[nt][2 * rs], oacc[nt][2 * rs + 1]);
            }
        }
    }
}

// ---------------------------------------------------------------------------
// Kernel C: FC + residual + LayerNorm. 256 threads, 32-row tile, 3 CTAs/SM.
// Warp tile 16x64, 8 warps (2x4); LN rows complete within CTA.
// ---------------------------------------------------------------------------
#define FC_A_STG (32 * SW)
#define FC_B_STG (256 * SW)
#define FC_SMEM_BYTES ((2 * FC_A_STG + 2 * FC_B_STG + 256) * 4)   // 47104

__global__ __launch_bounds__(256, 3) void fc_ln_kernel(
    const float* __restrict__ bfc, const float* __restrict__ resid,
    const float* __restrict__ ln_w, const float* __restrict__ ln_b,
    float* __restrict__ out)
{
    extern __shared__ u32 dyn[];
    u32*  As  = dyn;                               // [2][32*SW]
    u32*  Bs  = dyn + 2 * FC_A_STG;                // [2][256*SW]
    float* red = (float*)(dyn + 2 * FC_A_STG + 2 * FC_B_STG);   // [32][8]

    const u32* Wt = g_wh + 3 * 32768;
    const int tid  = threadIdx.x;
    const int wid  = tid >> 5;
    const int lane = tid & 31;
    const int g    = lane >> 2;
    const int t    = lane & 3;
    const int lr   = lane & 15;
    const int lc   = (lane >> 4) * 4;
    const int wm   = wid >> 2;   // 0..1
    const int wn   = wid & 3;    // 0..3
    const size_t m0 = (size_t)blockIdx.x * 32;

    const u32 as_b = smem_u32(As);
    const u32 bs_b = smem_u32(Bs);

    #pragma unroll
    for (int st = 0; st < 2; st++) {
        if (tid < 128) {                      // A: 128 chunks
            int r = tid >> 2, c4 = tid & 3;
            cp16(as_b + (u32)(st * FC_A_STG + r * SW + c4 * 4) * 4,
                 &g_attnout[(m0 + r) * 128 + st * 16 + c4 * 4]);
        }
        #pragma unroll
        for (int j = 0; j < 4; j++) {         // B: 1024 chunks
            int idx = tid + j * 256; int r = idx >> 2, c4 = idx & 3;
            cp16(bs_b + (u32)(st * FC_B_STG + r * SW + c4 * 4) * 4,
                 &Wt[(size_t)r * 128 + st * 16 + c4 * 4]);
        }
        CP_COMMIT();
    }

    float acc[8][4];
    #pragma unroll
    for (int b = 0; b < 8; b++)
        #pragma unroll
        for (int c = 0; c < 4; c++) acc[b][c] = 0.0f;

    #pragma unroll 1
    for (int i = 0; i < 8; i++) {
        const int s = i & 1;
        if (i < 7) { CP_WAIT(1); } else { CP_WAIT(0); }
        __syncthreads();

        const u32 a0 = as_b + (u32)s * FC_A_STG * 4;
        const u32 b0 = bs_b + (u32)s * FC_B_STG * 4;
        #pragma unroll
        for (int c = 0; c < 2; c++) {
            u32 ra[4];
            ldmx4(ra, a0 + (u32)((wm * 16 + lr) * SW + c * 8 + lc) * 4);
            #pragma unroll
            for (int qq = 0; qq < 4; qq++) {
                u32 rb[4];
                ldmx4(rb, b0 + (u32)((wn * 64 + qq * 16 + lr) * SW + c * 8 + lc) * 4);
                mma_f16(acc[2 * qq],     ra, rb[0], rb[2]);
                mma_f16(acc[2 * qq + 1], ra, rb[1], rb[3]);
            }
        }
        __syncthreads();
        if (i < 6) {
            if (tid < 128) {
                int r = tid >> 2, c4 = tid & 3;
                cp16(as_b + (u32)(s * FC_A_STG + r * SW + c4 * 4) * 4,
                     &g_attnout[(m0 + r) * 128 + (i + 2) * 16 + c4 * 4]);
            }
            #pragma unroll
            for (int j = 0; j < 4; j++) {
                int idx = tid + j * 256; int r = idx >> 2, c4 = idx & 3;
                cp16(bs_b + (u32)(s * FC_B_STG + r * SW + c4 * 4) * 4,
                     &Wt[(size_t)r * 128 + (i + 2) * 16 + c4 * 4]);
            }
            CP_COMMIT();
        }
    }

    // bias + residual + row stats
    #pragma unroll
    for (int rs = 0; rs < 2; rs++) {
        int rloc = wm * 16 + g + 8 * rs;
        float s = 0.0f, sq = 0.0f;
        #pragma unroll
        for (int nt = 0; nt < 8; nt++) {
            int col = wn * 64 + nt * 8 + 2 * t;
            float2 rr = *(const float2*)&resid[(m0 + rloc) * 256 + col];
            float v0 = acc[nt][2 * rs]     + bfc[col]     + rr.x;
            float v1 = acc[nt][2 * rs + 1] + bfc[col + 1] + rr.y;
            acc[nt][2 * rs]     = v0;
            acc[nt][2 * rs + 1] = v1;
            s  += v0 + v1;
            sq += v0 * v0 + v1 * v1;
        }
        s  += __shfl_xor_sync(0xffffffffu, s, 1);
        s  += __shfl_xor_sync(0xffffffffu, s, 2);
        sq += __shfl_xor_sync(0xffffffffu, sq, 1);
        sq += __shfl_xor_sync(0xffffffffu, sq, 2);
        if (t == 0) {
            red[rloc * 8 + wn]     = s;
            red[rloc * 8 + 4 + wn] = sq;
        }
    }
    __syncthreads();

    #pragma unroll
    for (int rs = 0; rs < 2; rs++) {
        int rloc = wm * 16 + g + 8 * rs;
        float s  = red[rloc * 8 + 0] + red[rloc * 8 + 1] + red[rloc * 8 + 2] + red[rloc * 8 + 3];
        float sq = red[rloc * 8 + 4] + red[rloc * 8 + 5] + red[rloc * 8 + 6] + red[rloc * 8 + 7];
        float mu   = s * (1.0f / 256.0f);
        float var  = sq * (1.0f / 256.0f) - mu * mu;
        float rstd = rsqrtf(var + 1e-6f);
        #pragma unroll
        for (int nt = 0; nt < 8; nt++) {
            int col = wn * 64 + nt * 8 + 2 * t;
            float2 lw = *(const float2*)&ln_w[col];
            float2 lb = *(const float2*)&ln_b[col];
            float2 o;
            o.x = (acc[nt][2 * rs]     - mu) * rstd * lw.x + lb.x;
            o.y = (acc[nt][2 * rs + 1] - mu) * rstd * lw.y + lb.y;
            *(float2*)&out[(m0 + rloc) * 256 + col] = o;
        }
    }
}

// ---------------------------------------------------------------------------
extern "C" void kernel_launch(void* const* d_in, const int* in_sizes, int n_in,
                              void* d_out, int out_size)
{
    const float* q    = (const float*)d_in[0];
    const float* k    = (const float*)d_in[1];
    const float* v    = (const float*)d_in[2];
    const float* Wq   = (const float*)d_in[3];
    const float* bq   = (const float*)d_in[4];
    const float* Wk   = (const float*)d_in[5];
    const float* bk   = (const float*)d_in[6];
    const float* Wv   = (const float*)d_in[7];
    const float* bv   = (const float*)d_in[8];
    const float* Wfc  = (const float*)d_in[9];
    const float* bfc  = (const float*)d_in[10];
    const float* ln_w = (const float*)d_in[11];
    const float* ln_b = (const float*)d_in[12];

    float* out  = (float*)d_out;
    float* attn = out + OUT_ELEMS;

    static bool attr_set = false;
    if (!attr_set) {
        cudaFuncSetAttribute(gemm_proj,    cudaFuncAttributeMaxDynamicSharedMemorySize, PJ_SMEM_BYTES);
        cudaFuncSetAttribute(attn_kernel,  cudaFuncAttributeMaxDynamicSharedMemorySize, AT_SMEM_BYTES);
        cudaFuncSetAttribute(fc_ln_kernel, cudaFuncAttributeMaxDynamicSharedMemorySize, FC_SMEM_BYTES);
        attr_set = true;
    }

    wconv<<<128, 256>>>(Wq, Wk, Wv, Wfc);
    gemm_proj<<<dim3(2048, 3), 256, PJ_SMEM_BYTES>>>(q, k, v, bq, bk, bv);
    attn_kernel<<<NBLH / 2, 256, AT_SMEM_BYTES>>>(attn);
    fc_ln_kernel<<<2048, 256, FC_SMEM_BYTES>>>(bfc, q, ln_w, ln_b, out);
}

// round 16
// speedup vs baseline: 1.1817x; 1.1817x over previous
#include <cuda_runtime.h>
#include <cuda_fp16.h>
#include <math.h>
#include <stdint.h>

typedef uint32_t u32;

#define MROWS 65536
#define NBLH  4096
#define OUT_ELEMS ((size_t)MROWS * 256)

// Scratch: fp16 pairs packed in u32 words (pairs along the k/d dimension)
__device__ u32 g_qh[(size_t)NBLH * 128 * 16];   // [blq][h][w][dk/2]
__device__ u32 g_kh[(size_t)NBLH * 128 * 16];
__device__ u32 g_vh[(size_t)NBLH * 128 * 16];
__device__ u32 g_attnout[(size_t)MROWS * 128];  // [m][d/2]
__device__ u32 g_wh[4 * 32768];                 // Wq,Wk,Wv,Wfc as fp16 pairs [n][k/2]

// ---------------------------------------------------------------------------
// helpers
// ---------------------------------------------------------------------------
__device__ __forceinline__ u32 f2h2(float lo, float hi) {
    __half2 h = __floats2half2_rn(lo, hi);
    return *reinterpret_cast<u32*>(&h);
}
__device__ __forceinline__ void mma_f16(float* d, const u32* a, u32 b0, u32 b1) {
    asm volatile(
        "mma.sync.aligned.m16n8k16.row.col.f32.f16.f16.f32 "
        "{%0,%1,%2,%3}, {%4,%5,%6,%7}, {%8,%9}, {%0,%1,%2,%3};"
        : "+f"(d[0]), "+f"(d[1]), "+f"(d[2]), "+f"(d[3])
        : "r"(a[0]), "r"(a[1]), "r"(a[2]), "r"(a[3]), "r"(b0), "r"(b1));
}
__device__ __forceinline__ void ldmx4(u32* r, u32 addr) {
    asm volatile("ldmatrix.sync.aligned.m8n8.x4.shared.b16 {%0,%1,%2,%3}, [%4];"
        : "=r"(r[0]), "=r"(r[1]), "=r"(r[2]), "=r"(r[3]) : "r"(addr));
}
__device__ __forceinline__ void ldmx4t(u32* r, u32 addr) {
    asm volatile("ldmatrix.sync.aligned.m8n8.x4.trans.shared.b16 {%0,%1,%2,%3}, [%4];"
        : "=r"(r[0]), "=r"(r[1]), "=r"(r[2]), "=r"(r[3]) : "r"(addr));
}
__device__ __forceinline__ u32 smem_u32(const void* p) {
    u32 a;
    asm("{ .reg .u64 t; cvta.to.shared.u64 t, %1; cvt.u32.u64 %0, t; }" : "=r"(a) : "l"(p));
    return a;
}
__device__ __forceinline__ void cp16(u32 dst, const void* src) {
    asm volatile("cp.async.cg.shared.global [%0], [%1], 16;" :: "r"(dst), "l"(src));
}
__device__ __forceinline__ void st_cs_f2(float* p, float x, float y) {
    asm volatile("st.global.cs.v2.f32 [%0], {%1,%2};" :: "l"(p), "f"(x), "f"(y) : "memory");
}
#define CP_COMMIT() asm volatile("cp.async.commit_group;")
#define CP_WAIT(n)  asm volatile("cp.async.wait_group %0;" :: "n"(n))

// row stride in u32 words for all [row][k] smem tiles (16 data + 4 pad)
#define SW 20

// ---------------------------------------------------------------------------
// Weight pre-conversion to packed fp16
// ---------------------------------------------------------------------------
__global__ void wconv(const float* __restrict__ Wq, const float* __restrict__ Wk,
                      const float* __restrict__ Wv, const float* __restrict__ Wfc)
{
    int i = blockIdx.x * 256 + threadIdx.x;   // 0..32767
    g_wh[i]             = f2h2(Wq[2 * i],  Wq[2 * i + 1]);
    g_wh[32768 + i]     = f2h2(Wk[2 * i],  Wk[2 * i + 1]);
    g_wh[2 * 32768 + i] = f2h2(Wv[2 * i],  Wv[2 * i + 1]);
    g_wh[3 * 32768 + i] = f2h2(Wfc[2 * i], Wfc[2 * i + 1]);
}

// ---------------------------------------------------------------------------
// Kernel A: QKV projection. 256 threads, 64-row m-tile, N=256, 8 warps (2x4),
// warp tile 32x64, BK=32, 2-stage pipeline. 2 CTAs/SM. grid (1024, 3).
// (round-14 version, measured best)
// ---------------------------------------------------------------------------
#define PJ_A_STG (64 * SW)            // 1280 words per A stage
#define PJ_B_STG (256 * SW)           // 5120 words per B stage
#define PJ_SMEM_BYTES ((2 * PJ_A_STG + 2 * PJ_B_STG) * 4)   // 51200

__global__ __launch_bounds__(256, 2) void gemm_proj(
    const float* __restrict__ q, const float* __restrict__ k, const float* __restrict__ v,
    const float* __restrict__ bq, const float* __restrict__ bk, const float* __restrict__ bv)
{
    extern __shared__ u32 dyn[];
    u32* As = dyn;                    // [2][64*SW]
    u32* Bs = dyn + 2 * PJ_A_STG;     // [2][256*SW]

    const int z = blockIdx.y;
    const float* X    = (z == 0) ? q : (z == 1) ? k : v;
    const u32*   Wt   = g_wh + (size_t)z * 32768;
    const float* bias = (z == 0) ? bq : (z == 1) ? bk : bv;
    u32*         outp = (z == 0) ? g_qh : (z == 1) ? g_kh : g_vh;
    const float scale = (z == 0) ? 0.17677669529663687f : 1.0f;

    const int tid  = threadIdx.x;
    const int wid  = tid >> 5;
    const int lane = tid & 31;
    const int g    = lane >> 2;
    const int t    = lane & 3;
    const int lr   = lane & 15;
    const int lc   = (lane >> 4) * 4;
    const int wm   = wid >> 2;     // 0..1
    const int wn   = wid & 3;      // 0..3
    const int m0   = blockIdx.x * 64;

    const u32 as_b = smem_u32(As);
    const u32 bs_b = smem_u32(Bs);

    const int arow = tid >> 2;     // 0..63 (4 threads per row)
    const int aq   = tid & 3;      // 8 floats each

    float4 fa[2];
#define LDG_A(cc)                                                              \
    do {                                                                       \
        size_t _o = (size_t)(m0 + arow) * 256 + (cc) * 32 + aq * 8;            \
        fa[0] = *(const float4*)&X[_o]; fa[1] = *(const float4*)&X[_o + 4];    \
    } while (0)
#define STS_A(st)                                                              \
    do {                                                                       \
        u32* _d = &As[(st) * PJ_A_STG + arow * SW + aq * 4];                   \
        _d[0] = f2h2(fa[0].x, fa[0].y); _d[1] = f2h2(fa[0].z, fa[0].w);        \
        _d[2] = f2h2(fa[1].x, fa[1].y); _d[3] = f2h2(fa[1].z, fa[1].w);        \
    } while (0)
#define CP_B(st, cc)                                                           \
    do {                                                                       \
        _Pragma("unroll")                                                      \
        for (int _j = 0; _j < 4; _j++) {                                       \
            int _idx = tid + _j * 256; int _r = _idx >> 2, _c4 = _idx & 3;     \
            cp16(bs_b + (u32)((st) * PJ_B_STG + _r * SW + _c4 * 4) * 4,        \
                 &Wt[(size_t)_r * 128 + (cc) * 16 + _c4 * 4]);                 \
        }                                                                      \
    } while (0)

    // prologue
    LDG_A(0);
    CP_B(0, 0); CP_COMMIT();
    STS_A(0);
    LDG_A(1);
    CP_B(1, 1); CP_COMMIT();

    float acc[2][8][4];
    #pragma unroll
    for (int a = 0; a < 2; a++)
        #pragma unroll
        for (int b = 0; b < 8; b++)
            #pragma unroll
            for (int c = 0; c < 4; c++) acc[a][b][c] = 0.0f;

    #pragma unroll 1
    for (int i = 0; i < 8; i++) {
        const int s = i & 1;
        if (i < 7) { CP_WAIT(1); } else { CP_WAIT(0); }
        __syncthreads();

        const u32 a0 = as_b + (u32)s * PJ_A_STG * 4;
        const u32 b0 = bs_b + (u32)s * PJ_B_STG * 4;
        #pragma unroll
        for (int c = 0; c < 2; c++) {
            u32 ra[2][4];
            #pragma unroll
            for (int mt = 0; mt < 2; mt++)
                ldmx4(ra[mt], a0 + (u32)((wm * 32 + mt * 16 + lr) * SW + c * 8 + lc) * 4);
            #pragma unroll
            for (int qq = 0; qq < 4; qq++) {
                u32 rb[4];
                ldmx4(rb, b0 + (u32)((wn * 64 + qq * 16 + lr) * SW + c * 8 + lc) * 4);
                #pragma unroll
                for (int mt = 0; mt < 2; mt++) {
                    mma_f16(acc[mt][2 * qq],     ra[mt], rb[0], rb[2]);
                    mma_f16(acc[mt][2 * qq + 1], ra[mt], rb[1], rb[3]);
                }
            }
        }

        if (i < 7) STS_A(s ^ 1);
        __syncthreads();
        if (i < 6) {
            LDG_A(i + 2);
            CP_B(s, i + 2);
            CP_COMMIT();
        }
    }

    // epilogue: bias, scale, pack fp16 pairs, scatter to [blq][h][w][dk/2]
    const int blq  = blockIdx.x >> 1;
    const int half = (blockIdx.x & 1) * 64;
    #pragma unroll
    for (int mt = 0; mt < 2; mt++) {
        #pragma unroll
        for (int nt = 0; nt < 8; nt++) {
            int n  = wn * 64 + nt * 8 + 2 * t;
            int h  = n >> 5;
            int dw = (n & 31) >> 1;
            float b0v = bias[n], b1v = bias[n + 1];
            #pragma unroll
            for (int rs = 0; rs < 2; rs++) {
                int ww = half + wm * 32 + mt * 16 + g + 8 * rs;
                outp[(((size_t)blq * 8 + h) * 128 + ww) * 16 + dw] =
                    f2h2((acc[mt][nt][2 * rs]     + b0v) * scale,
                         (acc[mt][nt][2 * rs + 1] + b1v) * scale);
            }
        }
    }
}

// ---------------------------------------------------------------------------
// Kernel B: attention, 2 blocks per CTA, cp.async double-buffered QKV.
// Round-14 version + (a) PV before prob writes, (b) st.global.cs prob writes.
// ---------------------------------------------------------------------------
#define AT_STG_W (3 * 128 * SW)               // 7680 words per stage (Q,K,V)
#define AT_SMEM_BYTES (2 * AT_STG_W * 4)      // 61440

__global__ __launch_bounds__(256, 2) void attn_kernel(float* __restrict__ attn_out)
{
    extern __shared__ u32 dyn[];
    const u32 sb = smem_u32(dyn);

    const int bid  = blockIdx.x;
    const int tid  = threadIdx.x;
    const int wid  = tid >> 5;
    const int lane = tid & 31;
    const int g    = lane >> 2;
    const int t    = lane & 3;
    const int lr   = lane & 15;
    const int lc   = (lane >> 4) * 4;

    // prologue: issue cp.async for both blocks' Q/K/V
    #pragma unroll
    for (int s = 0; s < 2; s++) {
        const size_t blk = (size_t)(bid * 2 + s);
        const u32* Qg = g_qh + blk * 2048;
        const u32* Kg = g_kh + blk * 2048;
        const u32* Vg = g_vh + blk * 2048;
        #pragma unroll
        for (int j = 0; j < 2; j++) {
            int idx = tid + j * 256;
            int row = idx >> 2, q4 = idx & 3;
            u32 off = sb + (u32)(s * AT_STG_W + row * SW + q4 * 4) * 4;
            cp16(off,                     Qg + idx * 4);
            cp16(off + 128 * SW * 4,      Kg + idx * 4);
            cp16(off + 2 * 128 * SW * 4,  Vg + idx * 4);
        }
        CP_COMMIT();
    }

    #pragma unroll 1
    for (int s = 0; s < 2; s++) {
        if (s == 0) { CP_WAIT(1); } else { CP_WAIT(0); }
        __syncthreads();

        const int blk  = bid * 2 + s;
        const u32 qs_b = sb + (u32)(s * AT_STG_W) * 4;
        const u32 ks_b = qs_b + 128 * SW * 4;
        const u32 vs_b = ks_b + 128 * SW * 4;

        // S = Q K^T : 16 rows x 128 cols per warp
        float sacc[16][4];
        #pragma unroll
        for (int nt = 0; nt < 16; nt++)
            #pragma unroll
            for (int c = 0; c < 4; c++) sacc[nt][c] = 0.0f;

        const int rbase16 = wid * 16;
        const int rbase   = rbase16 + g;
        #pragma unroll
        for (int c = 0; c < 2; c++) {
            u32 ra[4];
            ldmx4(ra, qs_b + (u32)((rbase16 + lr) * SW + c * 8 + lc) * 4);
            #pragma unroll
            for (int qq = 0; qq < 8; qq++) {
                u32 rb[4];
                ldmx4(rb, ks_b + (u32)((qq * 16 + lr) * SW + c * 8 + lc) * 4);
                mma_f16(sacc[2 * qq],     ra, rb[0], rb[2]);
                mma_f16(sacc[2 * qq + 1], ra, rb[1], rb[3]);
            }
        }

        // softmax (rows shared within lane quads via xor 1,2)
        float inv[2];
        #pragma unroll
        for (int rs = 0; rs < 2; rs++) {
            float mx = -1e30f;
            #pragma unroll
            for (int nt = 0; nt < 16; nt++) {
                mx = fmaxf(mx, sacc[nt][2 * rs]);
                mx = fmaxf(mx, sacc[nt][2 * rs + 1]);
            }
            mx = fmaxf(mx, __shfl_xor_sync(0xffffffffu, mx, 1));
            mx = fmaxf(mx, __shfl_xor_sync(0xffffffffu, mx, 2));
            float ss = 0.0f;
            #pragma unroll
            for (int nt = 0; nt < 16; nt++) {
                float e0 = __expf(sacc[nt][2 * rs] - mx);
                float e1 = __expf(sacc[nt][2 * rs + 1] - mx);
                sacc[nt][2 * rs] = e0; sacc[nt][2 * rs + 1] = e1;
                ss += e0 + e1;
            }
            ss += __shfl_xor_sync(0xffffffffu, ss, 1);
            ss += __shfl_xor_sync(0xffffffffu, ss, 2);
            inv[rs] = 1.0f / ss;
        }
        #pragma unroll
        for (int nt = 0; nt < 16; nt++) {
            sacc[nt][0] *= inv[0]; sacc[nt][1] *= inv[0];
            sacc[nt][2] *= inv[1]; sacc[nt][3] *= inv[1];
        }

        // O = P V first (keeps mma off the store-dependency path)
        float oacc[4][4];
        #pragma unroll
        for (int nt = 0; nt < 4; nt++)
            #pragma unroll
            for (int c = 0; c < 4; c++) oacc[nt][c] = 0.0f;

        const int vrow_off = ((lane >> 3) & 1) * 8 + (lane & 7);
        const int vcol_off = (lane >> 4) * 4;
        #pragma unroll
        for (int ks = 0; ks < 8; ks++) {
            u32 af[4];
            af[0] = f2h2(sacc[2 * ks][0],     sacc[2 * ks][1]);
            af[1] = f2h2(sacc[2 * ks][2],     sacc[2 * ks][3]);
            af[2] = f2h2(sacc[2 * ks + 1][0], sacc[2 * ks + 1][1]);
            af[3] = f2h2(sacc[2 * ks + 1][2], sacc[2 * ks + 1][3]);
            #pragma unroll
            for (int np = 0; np < 2; np++) {
                u32 rb[4];
                ldmx4t(rb, vs_b + (u32)((16 * ks + vrow_off) * SW + np * 8 + vcol_off) * 4);
                mma_f16(oacc[2 * np],     af, rb[0], rb[1]);
                mma_f16(oacc[2 * np + 1], af, rb[2], rb[3]);
            }
        }

        // write attn probs (fp32, streaming — write-once data, bypass L2 reuse)
        const size_t abase = (size_t)blk * 16384;
        #pragma unroll
        for (int nt = 0; nt < 16; nt++) {
            int col = nt * 8 + 2 * t;
            st_cs_f2(&attn_out[abase + (size_t)rbase * 128 + col],       sacc[nt][0], sacc[nt][1]);
            st_cs_f2(&attn_out[abase + (size_t)(rbase + 8) * 128 + col], sacc[nt][2], sacc[nt][3]);
        }

        // store O as fp16 pairs to [m][d/2]
        const int blq = blk >> 3;
        const int h   = blk & 7;
        #pragma unroll
        for (int nt = 0; nt < 4; nt++) {
            #pragma unroll
            for (int rs = 0; rs < 2; rs++) {
                int m = blq * 128 + rbase + 8 * rs;
                g_attnout[(size_t)m * 128 + h * 16 + nt * 4 + t] =
                    f2h2(oacc[nt][2 * rs], oacc[nt][2 * rs + 1]);
            }
        }
    }
}

// ---------------------------------------------------------------------------
// Kernel C: FC + residual + LayerNorm. 256 threads, 64-row tile, 2 CTAs/SM.
// (round-14 version, measured 62us)
// ---------------------------------------------------------------------------
#define FC_A_STG (64 * SW)
#define FC_B_STG (256 * SW)
#define FC_SMEM_BYTES ((2 * FC_A_STG + 2 * FC_B_STG + 512) * 4)   // 53248

__global__ __launch_bounds__(256, 2) void fc_ln_kernel(
    const float* __restrict__ bfc, const float* __restrict__ resid,
    const float* __restrict__ ln_w, const float* __restrict__ ln_b,
    float* __restrict__ out)
{
    extern __shared__ u32 dyn[];
    u32*  As  = dyn;                               // [2][64*SW]
    u32*  Bs  = dyn + 2 * FC_A_STG;                // [2][256*SW]
    float* red = (float*)(dyn + 2 * FC_A_STG + 2 * FC_B_STG);   // [64][8]

    const u32* Wt = g_wh + 3 * 32768;
    const int tid  = threadIdx.x;
    const int wid  = tid >> 5;
    const int lane = tid & 31;
    const int g    = lane >> 2;
    const int t    = lane & 3;
    const int lr   = lane & 15;
    const int lc   = (lane >> 4) * 4;
    const int wm   = wid >> 2;   // 0..1
    const int wn   = wid & 3;    // 0..3
    const size_t m0 = (size_t)blockIdx.x * 64;

    const u32 as_b = smem_u32(As);
    const u32 bs_b = smem_u32(Bs);

    #pragma unroll
    for (int st = 0; st < 2; st++) {
        {
            int r = tid >> 2, c4 = tid & 3;   // A: 256 chunks, 1/thread
            cp16(as_b + (u32)(st * FC_A_STG + r * SW + c4 * 4) * 4,
                 &g_attnout[(m0 + r) * 128 + st * 16 + c4 * 4]);
        }
        #pragma unroll
        for (int j = 0; j < 4; j++) {         // B: 1024 chunks, 4/thread
            int idx = tid + j * 256; int r = idx >> 2, c4 = idx & 3;
            cp16(bs_b + (u32)(st * FC_B_STG + r * SW + c4 * 4) * 4,
                 &Wt[(size_t)r * 128 + st * 16 + c4 * 4]);
        }
        CP_COMMIT();
    }

    float acc[2][8][4];
    #pragma unroll
    for (int a = 0; a < 2; a++)
        #pragma unroll
        for (int b = 0; b < 8; b++)
            #pragma unroll
            for (int c = 0; c < 4; c++) acc[a][b][c] = 0.0f;

    #pragma unroll 1
    for (int i = 0; i < 8; i++) {
        const int s = i & 1;
        if (i < 7) { CP_WAIT(1); } else { CP_WAIT(0); }
        __syncthreads();

        const u32 a0 = as_b + (u32)s * FC_A_STG * 4;
        const u32 b0 = bs_b + (u32)s * FC_B_STG * 4;
        #pragma unroll
        for (int c = 0; c < 2; c++) {
            u32 ra[2][4];
            #pragma unroll
            for (int mt = 0; mt < 2; mt++)
                ldmx4(ra[mt], a0 + (u32)((wm * 32 + mt * 16 + lr) * SW + c * 8 + lc) * 4);
            #pragma unroll
            for (int qq = 0; qq < 4; qq++) {
                u32 rb[4];
                ldmx4(rb, b0 + (u32)((wn * 64 + qq * 16 + lr) * SW + c * 8 + lc) * 4);
                #pragma unroll
                for (int mt = 0; mt < 2; mt++) {
                    mma_f16(acc[mt][2 * qq],     ra[mt], rb[0], rb[2]);
                    mma_f16(acc[mt][2 * qq + 1], ra[mt], rb[1], rb[3]);
                }
            }
        }
        __syncthreads();
        if (i < 6) {
            {
                int r = tid >> 2, c4 = tid & 3;
                cp16(as_b + (u32)(s * FC_A_STG + r * SW + c4 * 4) * 4,
                     &g_attnout[(m0 + r) * 128 + (i + 2) * 16 + c4 * 4]);
            }
            #pragma unroll
            for (int j = 0; j < 4; j++) {
                int idx = tid + j * 256; int r = idx >> 2, c4 = idx & 3;
                cp16(bs_b + (u32)(s * FC_B_STG + r * SW + c4 * 4) * 4,
                     &Wt[(size_t)r * 128 + (i + 2) * 16 + c4 * 4]);
            }
            CP_COMMIT();
        }
    }

    // bias + residual + row stats
    #pragma unroll
    for (int mt = 0; mt < 2; mt++) {
        #pragma unroll
        for (int rs = 0; rs < 2; rs++) {
            int rloc = wm * 32 + mt * 16 + g + 8 * rs;
            float s = 0.0f, sq = 0.0f;
            #pragma unroll
            for (int nt = 0; nt < 8; nt++) {
                int col = wn * 64 + nt * 8 + 2 * t;
                float2 rr = *(const float2*)&resid[(m0 + rloc) * 256 + col];
                float v0 = acc[mt][nt][2 * rs]     + bfc[col]     + rr.x;
                float v1 = acc[mt][nt][2 * rs + 1] + bfc[col + 1] + rr.y;
                acc[mt][nt][2 * rs]     = v0;
                acc[mt][nt][2 * rs + 1] = v1;
                s  += v0 + v1;
                sq += v0 * v0 + v1 * v1;
            }
            s  += __shfl_xor_sync(0xffffffffu, s, 1);
            s  += __shfl_xor_sync(0xffffffffu, s, 2);
            sq += __shfl_xor_sync(0xffffffffu, sq, 1);
            sq += __shfl_xor_sync(0xffffffffu, sq, 2);
            if (t == 0) {
                red[rloc * 8 + wn]     = s;
                red[rloc * 8 + 4 + wn] = sq;
            }
        }
    }
    __syncthreads();

    #pragma unroll
    for (int mt = 0; mt < 2; mt++) {
        #pragma unroll
        for (int rs = 0; rs < 2; rs++) {
            int rloc = wm * 32 + mt * 16 + g + 8 * rs;
            float s  = red[rloc * 8 + 0] + red[rloc * 8 + 1] + red[rloc * 8 + 2] + red[rloc * 8 + 3];
            float sq = red[rloc * 8 + 4] + red[rloc * 8 + 5] + red[rloc * 8 + 6] + red[rloc * 8 + 7];
            float mu   = s * (1.0f / 256.0f);
            float var  = sq * (1.0f / 256.0f) - mu * mu;
            float rstd = rsqrtf(var + 1e-6f);
            #pragma unroll
            for (int nt = 0; nt < 8; nt++) {
                int col = wn * 64 + nt * 8 + 2 * t;
                float2 lw = *(const float2*)&ln_w[col];
                float2 lb = *(const float2*)&ln_b[col];
                float2 o;
                o.x = (acc[mt][nt][2 * rs]     - mu) * rstd * lw.x + lb.x;
                o.y = (acc[mt][nt][2 * rs + 1] - mu) * rstd * lw.y + lb.y;
                *(float2*)&out[(m0 + rloc) * 256 + col] = o;
            }
        }
    }
}

// ---------------------------------------------------------------------------
extern "C" void kernel_launch(void* const* d_in, const int* in_sizes, int n_in,
                              void* d_out, int out_size)
{
    const float* q    = (const float*)d_in[0];
    const float* k    = (const float*)d_in[1];
    const float* v    = (const float*)d_in[2];
    const float* Wq   = (const float*)d_in[3];
    const float* bq   = (const float*)d_in[4];
    const float* Wk   = (const float*)d_in[5];
    const float* bk   = (const float*)d_in[6];
    const float* Wv   = (const float*)d_in[7];
    const float* bv   = (const float*)d_in[8];
    const float* Wfc  = (const float*)d_in[9];
    const float* bfc  = (const float*)d_in[10];
    const float* ln_w = (const float*)d_in[11];
    const float* ln_b = (const float*)d_in[12];

    float* out  = (float*)d_out;
    float* attn = out + OUT_ELEMS;

    static bool attr_set = false;
    if (!attr_set) {
        cudaFuncSetAttribute(gemm_proj,    cudaFuncAttributeMaxDynamicSharedMemorySize, PJ_SMEM_BYTES);
        cudaFuncSetAttribute(attn_kernel,  cudaFuncAttributeMaxDynamicSharedMemorySize, AT_SMEM_BYTES);
        cudaFuncSetAttribute(fc_ln_kernel, cudaFuncAttributeMaxDynamicSharedMemorySize, FC_SMEM_BYTES);
        attr_set = true;
    }

    wconv<<<128, 256>>>(Wq, Wk, Wv, Wfc);
    gemm_proj<<<dim3(1024, 3), 256, PJ_SMEM_BYTES>>>(q, k, v, bq, bk, bv);
    attn_kernel<<<NBLH / 2, 256, AT_SMEM_BYTES>>>(attn);
    fc_ln_kernel<<<1024, 256, FC_SMEM_BYTES>>>(bfc, q, ln_w, ln_b, out);
}